// round 13
// baseline (speedup 1.0000x reference)
#include <cuda_runtime.h>
#include <math.h>

// Fixed shapes: x (4, 32, 8192, 64) fp32, token_positions = arange(8192)
#define SEQ       8192
#define NF4_ROW   16                    // 64 floats / 4 per row
#define SLICE_F4  (SEQ * NF4_ROW)       // 131072 float4 per (b,h) slice
#define N4_TOTAL  (128 * SLICE_F4)      // 16,777,216 float4 total
#define HALF_F4   (N4_TOTAL / 2)        // = 64 * SLICE_F4 -> streams share (p,j)
#define LOG2_THETA 13.2877123795494489f // log2(10000), fp32

#define NSM       148
#define BLKS_PER  8
#define NBLOCKS   (NSM * BLKS_PER)      // 1184 persistent CTAs
#define NTHREADS  (NBLOCKS * 256)       // 303,104

// R9's winning inner body (2 front-batched loads, shared inline trig, plain
// LDG/STG — every cache hint lost in R8/R11) inside a persistent grid-stride
// loop: exactly one wave, no 27.7-wave tail, no CTA launch churn. __restrict__
// lets ptxas overlap iteration n+1 loads with iteration n stores.
__global__ void __launch_bounds__(256, 6)
rope_persist(const float4* __restrict__ x, float4* __restrict__ out,
             const int* __restrict__ pos) {
    int tid = blockIdx.x * 256 + threadIdx.x;

    for (int i = tid; i < HALF_F4; i += NTHREADS) {
        int j = i & (NF4_ROW - 1);               // float4 within row
        int p = (i >> 4) & (SEQ - 1);            // seq position

        // Front-batch both loads: latency covers the trig below.
        float4 v0 = x[i];
        float4 v1 = x[i + HALF_F4];

        float posf = (float)__ldg(&pos[p]);
        float invf0 = exp2f(-(float)(2 * j)     * (LOG2_THETA / 32.0f));
        float invf1 = exp2f(-(float)(2 * j + 1) * (LOG2_THETA / 32.0f));
        float c0, s0, c1, s1;
        sincosf(posf * invf0, &s0, &c0);
        sincosf(posf * invf1, &s1, &c1);

        float4 o;
        o.x = c0 * v0.x - s0 * v0.y;  o.y = s0 * v0.x + c0 * v0.y;
        o.z = c1 * v0.z - s1 * v0.w;  o.w = s1 * v0.z + c1 * v0.w;
        out[i] = o;
        o.x = c0 * v1.x - s0 * v1.y;  o.y = s0 * v1.x + c0 * v1.y;
        o.z = c1 * v1.z - s1 * v1.w;  o.w = s1 * v1.z + c1 * v1.w;
        out[i + HALF_F4] = o;
    }
}

extern "C" void kernel_launch(void* const* d_in, const int* in_sizes, int n_in,
                              void* d_out, int out_size) {
    const float4* x   = (const float4*)d_in[0];
    const int*    pos = (const int*)d_in[1];
    float4*       out = (float4*)d_out;

    rope_persist<<<NBLOCKS, 256>>>(x, out, pos);
}

// round 14
// speedup vs baseline: 1.1205x; 1.1205x over previous
#include <cuda_runtime.h>
#include <math.h>

// Fixed shapes: x (4, 32, 8192, 64) fp32, token_positions = arange(8192)
#define SEQ       8192
#define NF4_ROW   16                    // 64 floats / 4 per row
#define SLICE_F4  (SEQ * NF4_ROW)       // 131072 float4 per (b,h) slice
#define N4_TOTAL  (128 * SLICE_F4)      // 16,777,216 float4 total
#define HALF_F4   (N4_TOTAL / 2)        // = 64 * SLICE_F4 -> streams share (p,j)
#define LOG2_THETA 13.2877123795494489f // log2(10000), fp32

#define TPB 512                         // R14 knob: 512-thread blocks (was 256)

// R9 inner body verbatim (converged optimum: ILP=2 front-batched, shared
// inline trig, plain LDG/STG — cache hints/persistence/smem-tables/ILP4 all
// measured worse in R8-R13). Only change: block size 256 -> 512, halving CTA
// count at identical warp-level access pattern.
__global__ void __launch_bounds__(TPB, 3)
rope_inline(const float4* __restrict__ x, float4* __restrict__ out,
            const int* __restrict__ pos) {
    int i = blockIdx.x * TPB + threadIdx.x;      // 0 .. HALF_F4-1
    int j = i & (NF4_ROW - 1);                   // float4 within row
    int p = (i >> 4) & (SEQ - 1);                // seq position

    // ---- Front-batch both loads: DRAM latency covers the trig below ----
    float4 v0 = x[i];
    float4 v1 = x[i + HALF_F4];

    // ---- Inline trig for pairs k = 2j, 2j+1 (shared by both streams) ----
    float posf = (float)__ldg(&pos[p]);
    float invf0 = exp2f(-(float)(2 * j)     * (LOG2_THETA / 32.0f));
    float invf1 = exp2f(-(float)(2 * j + 1) * (LOG2_THETA / 32.0f));
    float c0, s0, c1, s1;
    sincosf(posf * invf0, &s0, &c0);
    sincosf(posf * invf1, &s1, &c1);

    // ---- Rotate + store ----
    float4 o;
    o.x = c0 * v0.x - s0 * v0.y;  o.y = s0 * v0.x + c0 * v0.y;
    o.z = c1 * v0.z - s1 * v0.w;  o.w = s1 * v0.z + c1 * v0.w;
    out[i] = o;
    o.x = c0 * v1.x - s0 * v1.y;  o.y = s0 * v1.x + c0 * v1.y;
    o.z = c1 * v1.z - s1 * v1.w;  o.w = s1 * v1.z + c1 * v1.w;
    out[i + HALF_F4] = o;
}

extern "C" void kernel_launch(void* const* d_in, const int* in_sizes, int n_in,
                              void* d_out, int out_size) {
    const float4* x   = (const float4*)d_in[0];
    const int*    pos = (const int*)d_in[1];
    float4*       out = (float4*)d_out;

    // 8,388,608 threads = 16384 blocks of 512
    rope_inline<<<HALF_F4 / TPB, TPB>>>(x, out, pos);
}